// round 16
// baseline (speedup 1.0000x reference)
#include <cuda_runtime.h>
#include <cuda_bf16.h>
#include <math.h>
#include <stdint.h>

// ---------------- problem constants ----------------
#define BP_  2
#define L_   32
#define N_   16
#define O_   64
#define D_   1024
#define AD_  1024
#define HEAD_ 128
#define W_   256
#define FH_  2048
#define M_   48
#define E_   64
#define S_   2048
#define EPS_ 1e-5f
#define MB1 (1u<<20)

// ---------------- device scratch (allocation-free) ----------------
__device__ float g_x   [BP_ * S_ * AD_];
__device__ float g_qkv [BP_ * S_ * 3 * AD_];
__device__ float g_xold[BP_ * L_ * M_ * AD_];
__device__ float g_xnew[BP_ * L_ * N_ * AD_];
__device__ float g_xnew2[BP_ * L_ * N_ * AD_];   // split-K partial z=1
__device__ float g_xnew3[BP_ * L_ * N_ * AD_];   // split-K partial z=2
__device__ float g_y   [BP_ * L_ * N_ * AD_];
__device__ float g_invf[64];

__device__ __nv_bfloat16 g_hh[BP_ * S_ * AD_],  g_hl[BP_ * S_ * AD_];
__device__ __nv_bfloat16 g_ah[BP_ * S_ * AD_],  g_al[BP_ * S_ * AD_];
__device__ __nv_bfloat16 g_gh[BP_ * S_ * FH_],  g_gl[BP_ * S_ * FH_];
__device__ __nv_bfloat16 g_ach[3u * MB1], g_acl[3u * MB1];
__device__ __nv_bfloat16 g_yh[MB1],    g_yl[MB1];
__device__ __nv_bfloat16 g_whi[27u * MB1], g_wlo[27u * MB1];

#define OFF_WOLD  0
#define OFF_WAGG  1
#define OFF_WQKV  2
#define OFF_WO    8
#define OFF_WUP   10  /* rows INTERLEAVED (a,b pairs) */
#define OFF_WDOWN 18
#define OFF_WP2   22
#define OFF_WP3   24

// ---------------- small helpers ----------------
__device__ __forceinline__ void bsplit(float f, __nv_bfloat16& h, __nv_bfloat16& l) {
    h = __float2bfloat16(f);
    l = __float2bfloat16(f - __bfloat162float(h));
}

__device__ __forceinline__ float blk_sum(float v, float* red) {
    int lane = threadIdx.x & 31, w = threadIdx.x >> 5;
#pragma unroll
    for (int o = 16; o; o >>= 1) v += __shfl_xor_sync(0xffffffffu, v, o);
    if (lane == 0) red[w] = v;
    __syncthreads();
    int nw = (blockDim.x + 31) >> 5;
    if (threadIdx.x < 32) {
        float r = (threadIdx.x < nw) ? red[threadIdx.x] : 0.f;
#pragma unroll
        for (int o = 16; o; o >>= 1) r += __shfl_xor_sync(0xffffffffu, r, o);
        if (lane == 0) red[0] = r;
    }
    __syncthreads();
    float r = red[0];
    __syncthreads();
    return r;
}

// ---------------- PTX helpers ----------------
#define SWZ64(o) ((o) ^ (((o) >> 3) & 0x30))

static __device__ __forceinline__ uint32_t smem_u32(const void* p) {
    uint32_t a;
    asm("{ .reg .u64 t; cvta.to.shared.u64 t, %1; cvt.u32.u64 %0, t; }" : "=r"(a) : "l"(p));
    return a;
}
static __device__ __forceinline__ void cpa16(uint32_t dst, const void* src) {
    asm volatile("cp.async.cg.shared.global [%0], [%1], 16;" :: "r"(dst), "l"(src) : "memory");
}
static __device__ __forceinline__ void ldm4(uint32_t& r0, uint32_t& r1, uint32_t& r2,
                                            uint32_t& r3, uint32_t addr) {
    asm volatile("ldmatrix.sync.aligned.m8n8.x4.shared.b16 {%0,%1,%2,%3}, [%4];"
                 : "=r"(r0), "=r"(r1), "=r"(r2), "=r"(r3) : "r"(addr));
}
#define MMA16816(d, a, b) \
    asm volatile("mma.sync.aligned.m16n8k16.row.col.f32.bf16.bf16.f32 " \
        "{%0,%1,%2,%3}, {%4,%5,%6,%7}, {%8,%9}, {%0,%1,%2,%3};" \
        : "+f"((d)[0]), "+f"((d)[1]), "+f"((d)[2]), "+f"((d)[3]) \
        : "r"((a)[0]), "r"((a)[1]), "r"((a)[2]), "r"((a)[3]), "r"((b)[0]), "r"((b)[1]))

// ---------------- tensor-core split-bf16 GEMM (R11/R13 schedule) ----------------
// gridDim.z = split-K count: z picks K-slice [z*K, (z+1)*K); z==1 -> C2, z==2 -> C3.
// OMODE: 0 store fp32, 1 accumulate fp32, 2 store split bf16, 3 fused silu-gate.
template<int OMODE>
__global__ void __launch_bounds__(128, 2) tgemm_k(
    const __nv_bfloat16* __restrict__ Ah, const __nv_bfloat16* __restrict__ Al,
    const __nv_bfloat16* __restrict__ Bh, const __nv_bfloat16* __restrict__ Bl,
    float* __restrict__ C, float* __restrict__ C2, float* __restrict__ C3,
    __nv_bfloat16* __restrict__ Ch, __nv_bfloat16* __restrict__ Cl,
    int M, int N, int K, int lda, int ldb)
{
    extern __shared__ char smem[];
    uint32_t sb = smem_u32(smem);
    int tid = threadIdx.x, lane = tid & 31, wid = tid >> 5;
    int wm = wid & 1, wn = wid >> 1;
    int brow = blockIdx.y << 7, bcol = blockIdx.x << 7;
    int koff = blockIdx.z * K;
    if (blockIdx.z == 1) C = C2;
    if (blockIdx.z == 2) C = C3;

    const __nv_bfloat16* src0 = Ah + (size_t)brow * lda + koff;
    const __nv_bfloat16* src1 = Al + (size_t)brow * lda + koff;
    const __nv_bfloat16* src2 = Bh + (size_t)bcol * ldb + koff;
    const __nv_bfloat16* src3 = Bl + (size_t)bcol * ldb + koff;

    float d[4][8][4];
#pragma unroll
    for (int mi = 0; mi < 4; mi++)
#pragma unroll
        for (int ni = 0; ni < 8; ni++)
#pragma unroll
            for (int q = 0; q < 4; q++) d[mi][ni][q] = 0.f;

    const int nch = K >> 5;

    auto load_stage = [&](uint32_t stb, int k0) {
#pragma unroll
        for (int j = 0; j < 4; j++) {
            int u = tid + (j << 7);
            int row = u >> 2, un = u & 3;
            uint32_t doff = SWZ64((uint32_t)(row * 64 + un * 16));
            size_t ga = (size_t)row * lda + k0 + un * 8;
            size_t gb = (size_t)row * ldb + k0 + un * 8;
            cpa16(stb +     0 + doff, src0 + ga);
            cpa16(stb +  8192 + doff, src1 + ga);
            cpa16(stb + 16384 + doff, src2 + gb);
            cpa16(stb + 24576 + doff, src3 + gb);
        }
        asm volatile("cp.async.commit_group;" ::: "memory");
    };

    load_stage(sb, 0);
    if (nch > 1) load_stage(sb + 32768, 32);

    int g = lane >> 3, r = lane & 7;
    for (int i = 0; i < nch; i++) {
        if (i + 1 < nch) { asm volatile("cp.async.wait_group 1;" ::: "memory"); }
        else             { asm volatile("cp.async.wait_group 0;" ::: "memory"); }
        __syncthreads();
        if (i + 2 < nch) {
            int s = (i + 2) % 3;
            load_stage(sb + (uint32_t)(s * 32768), (i + 2) << 5);
        }
        uint32_t stb = sb + (uint32_t)((i % 3) * 32768);

#pragma unroll
        for (int ks = 0; ks < 2; ks++) {
            uint32_t ah[4][4], al[4][4], bh[8][2], bl[8][2];
#pragma unroll
            for (int mi = 0; mi < 4; mi++) {
                int row = wm * 64 + mi * 16 + (g & 1) * 8 + r;
                int colb = ks * 32 + (g >> 1) * 16;
                uint32_t off = SWZ64((uint32_t)(row * 64 + colb));
                ldm4(ah[mi][0], ah[mi][1], ah[mi][2], ah[mi][3], stb + off);
                ldm4(al[mi][0], al[mi][1], al[mi][2], al[mi][3], stb + 8192 + off);
            }
#pragma unroll
            for (int n2 = 0; n2 < 4; n2++) {
                int rown = wn * 64 + n2 * 16 + (g >> 1) * 8 + r;
                int colb = ks * 32 + (g & 1) * 16;
                uint32_t off = SWZ64((uint32_t)(rown * 64 + colb));
                ldm4(bh[2*n2][0], bh[2*n2][1], bh[2*n2+1][0], bh[2*n2+1][1], stb + 16384 + off);
                ldm4(bl[2*n2][0], bl[2*n2][1], bl[2*n2+1][0], bl[2*n2+1][1], stb + 24576 + off);
            }
#pragma unroll
            for (int mi = 0; mi < 4; mi++)
#pragma unroll
                for (int ni = 0; ni < 8; ni++) MMA16816(d[mi][ni], ah[mi], bh[ni]);
#pragma unroll
            for (int mi = 0; mi < 4; mi++)
#pragma unroll
                for (int ni = 0; ni < 8; ni++) MMA16816(d[mi][ni], ah[mi], bl[ni]);
#pragma unroll
            for (int mi = 0; mi < 4; mi++)
#pragma unroll
                for (int ni = 0; ni < 8; ni++) MMA16816(d[mi][ni], al[mi], bh[ni]);
        }
    }

    // epilogue
#pragma unroll
    for (int mi = 0; mi < 4; mi++)
#pragma unroll
        for (int ni = 0; ni < 8; ni++) {
            int row = brow + wm * 64 + mi * 16 + (lane >> 2);
            int col = bcol + wn * 64 + ni * 8 + 2 * (lane & 3);
            if (OMODE == 3) {
                int gcol = col >> 1;
                int gn = N >> 1;
                float a0 = d[mi][ni][0], b0 = d[mi][ni][1];
                float a1 = d[mi][ni][2], b1 = d[mi][ni][3];
                float f0 = (a0 / (1.f + __expf(-a0))) * b0;
                float f1 = (a1 / (1.f + __expf(-a1))) * b1;
                __nv_bfloat16 h0, l0, h1, l1;
                bsplit(f0, h0, l0); bsplit(f1, h1, l1);
                Ch[(size_t)row * gn + gcol] = h0;
                Cl[(size_t)row * gn + gcol] = l0;
                Ch[(size_t)(row + 8) * gn + gcol] = h1;
                Cl[(size_t)(row + 8) * gn + gcol] = l1;
            } else if (OMODE == 2) {
                __nv_bfloat16 h0, h1, l0, l1;
                bsplit(d[mi][ni][0], h0, l0); bsplit(d[mi][ni][1], h1, l1);
                *(__nv_bfloat162*)(Ch + (size_t)row * N + col) = __nv_bfloat162(h0, h1);
                *(__nv_bfloat162*)(Cl + (size_t)row * N + col) = __nv_bfloat162(l0, l1);
                bsplit(d[mi][ni][2], h0, l0); bsplit(d[mi][ni][3], h1, l1);
                *(__nv_bfloat162*)(Ch + (size_t)(row + 8) * N + col) = __nv_bfloat162(h0, h1);
                *(__nv_bfloat162*)(Cl + (size_t)(row + 8) * N + col) = __nv_bfloat162(l0, l1);
            } else {
                float* p0 = C + (size_t)row * N + col;
                float* p1 = C + (size_t)(row + 8) * N + col;
                float2 v0 = make_float2(d[mi][ni][0], d[mi][ni][1]);
                float2 v1 = make_float2(d[mi][ni][2], d[mi][ni][3]);
                if (OMODE == 1) {
                    float2 o0 = *(const float2*)p0, o1 = *(const float2*)p1;
                    v0.x += o0.x; v0.y += o0.y; v1.x += o1.x; v1.y += o1.y;
                }
                *(float2*)p0 = v0;
                *(float2*)p1 = v1;
            }
        }
}

// ---------------- fused weight split ----------------
struct WSrc { const float* p[11]; };
__global__ void wsplit_all_k(WSrc ws, __nv_bfloat16* __restrict__ hi,
                             __nv_bfloat16* __restrict__ lo) {
    const unsigned char segOf[27] = {0,1, 2,2,2,2,2,2, 3,3, 4,4,4,4,4,4,4,4, 5,5,5,5, 6,7, 8,9,10};
    const unsigned char locOf[27] = {0,0, 0,1,2,3,4,5, 0,1, 0,1,2,3,4,5,6,7, 0,1,2,3, 0,0, 0,0,0};
    const unsigned char baseOf[27]= {0,1, 2,3,4,5,6,7, 8,9, 10,11,12,13,14,15,16,17, 18,19,20,21, 22,22, 24,24,24};
    const unsigned short strOf[27]= {1024,1024, 1024,1024,1024,1024,1024,1024, 1024,1024,
                                     1024,1024,1024,1024,1024,1024,1024,1024, 1024,1024,1024,1024,
                                     2048,2048, 3072,3072,3072};
    const unsigned short colOf[27]= {0,0, 0,0,0,0,0,0, 0,0, 0,0,0,0,0,0,0,0, 0,0,0,0,
                                     0,1024, 0,1024,2048};
    int unit = blockIdx.y;
    bool ileave = (unit >= 10 && unit <= 17);
    const float4* src = (const float4*)ws.p[segOf[unit]] + (size_t)locOf[unit] * (MB1 >> 2);
    for (int i = blockIdx.x * blockDim.x + threadIdx.x; i < (int)(MB1 >> 2);
         i += gridDim.x * blockDim.x) {
        float4 v = src[i];
        int row = i >> 8, c4 = i & 255;
        size_t e;
        if (ileave) {
            int layer = (unit - 10) >> 2, loc = (unit - 10) & 3;
            int grow = loc * 1024 + row;
            int drow = (grow < 2048) ? (grow * 2) : ((grow - 2048) * 2 + 1);
            e = (size_t)(OFF_WUP + 4 * layer) * MB1 + (size_t)drow * 1024 + c4 * 4;
        } else {
            e = (size_t)baseOf[unit] * MB1 + (size_t)row * strOf[unit] + colOf[unit] + c4 * 4;
        }
        __nv_bfloat16 h0, h1, h2, h3, l0, l1, l2, l3;
        bsplit(v.x, h0, l0); bsplit(v.y, h1, l1);
        bsplit(v.z, h2, l2); bsplit(v.w, h3, l3);
        *(__nv_bfloat162*)(hi + e)     = __nv_bfloat162(h0, h1);
        *(__nv_bfloat162*)(hi + e + 2) = __nv_bfloat162(h2, h3);
        *(__nv_bfloat162*)(lo + e)     = __nv_bfloat162(l0, l1);
        *(__nv_bfloat162*)(lo + e + 2) = __nv_bfloat162(l2, l3);
    }
}

// ---------------- one-time inv_freq table ----------------
__global__ void init_invf_k() {
    int j = threadIdx.x;
    if (j < 64) {
        double invf_d = exp(-(double)j * (9.210340371976184 / 64.0));
        g_invf[j] = (float)invf_d;
    }
}

// ---------------- rmsnorm -> split bf16 ----------------
__global__ void rmsnorm_k(const float* __restrict__ in, const float* __restrict__ w,
                          __nv_bfloat16* __restrict__ oh, __nv_bfloat16* __restrict__ ol,
                          int gsize, int gstride, int goff, int ostride, int ooff) {
    __shared__ float red[32];
    int r = blockIdx.x;
    int inrow = (r / gsize) * gstride + goff + (r % gsize);
    float4 v = ((const float4*)(in + (size_t)inrow * 1024))[threadIdx.x];
    float ss = v.x * v.x + v.y * v.y + v.z * v.z + v.w * v.w;
    ss = blk_sum(ss, red);
    float sc = rsqrtf(ss * (1.f / 1024.f) + EPS_);
    float4 wv = ((const float4*)w)[threadIdx.x];
    __nv_bfloat16 h0, h1, h2, h3, l0, l1, l2, l3;
    bsplit(v.x * sc * wv.x, h0, l0); bsplit(v.y * sc * wv.y, h1, l1);
    bsplit(v.z * sc * wv.z, h2, l2); bsplit(v.w * sc * wv.w, h3, l3);
    size_t o = (size_t)r * ostride + ooff + threadIdx.x * 4;
    *(__nv_bfloat162*)(oh + o)     = __nv_bfloat162(h0, h1);
    *(__nv_bfloat162*)(oh + o + 2) = __nv_bfloat162(h2, h3);
    *(__nv_bfloat162*)(ol + o)     = __nv_bfloat162(l0, l1);
    *(__nv_bfloat162*)(ol + o + 2) = __nv_bfloat162(l2, l3);
}

// ---------------- fused shifted-y + rmsnorm -> ach cols 2048..3071 ----------------
__global__ void yfrms_k(const float* __restrict__ y, const int* __restrict__ begin,
                        const float* __restrict__ pad_emb, const float* __restrict__ w,
                        __nv_bfloat16* __restrict__ oh, __nv_bfloat16* __restrict__ ol) {
    __shared__ float red[32];
    int r = blockIdx.x;
    int b = r >> 9, t = r & 511;
    int n = t & 15, l = t >> 4;
    bool cond = (n == 0) && (begin[b * 32 + l] != 0);
    const float* x = cond ? pad_emb : (y + ((size_t)b * 512 + ((t + 511) & 511)) * 1024);
    float4 v = ((const float4*)x)[threadIdx.x];
    float ss = v.x * v.x + v.y * v.y + v.z * v.z + v.w * v.w;
    ss = blk_sum(ss, red);
    float sc = rsqrtf(ss * (1.f / 1024.f) + EPS_);
    float4 wv = ((const float4*)w)[threadIdx.x];
    __nv_bfloat16 h0, h1, h2, h3, l0, l1, l2, l3;
    bsplit(v.x * sc * wv.x, h0, l0); bsplit(v.y * sc * wv.y, h1, l1);
    bsplit(v.z * sc * wv.z, h2, l2); bsplit(v.w * sc * wv.w, h3, l3);
    size_t o = (size_t)r * 3072 + 2048 + threadIdx.x * 4;
    *(__nv_bfloat162*)(oh + o)     = __nv_bfloat162(h0, h1);
    *(__nv_bfloat162*)(oh + o + 2) = __nv_bfloat162(h2, h3);
    *(__nv_bfloat162*)(ol + o)     = __nv_bfloat162(l0, l1);
    *(__nv_bfloat162*)(ol + o + 2) = __nv_bfloat162(l2, l3);
}

// ---------------- l2norm + rotary ----------------
__global__ void __launch_bounds__(256) qk_rope_k(float* __restrict__ qkv) {
    int s = blockIdx.x, b = blockIdx.y;
    int t = threadIdx.x, w = t >> 5, lane = t & 31;
#pragma unroll
    for (int si = 0; si < 2; si++) {
        int sg = w * 2 + si;
        int h = sg >> 1;
        int off = (sg & 1) ? 1024 : 0;
        float* p = qkv + ((size_t)(b * 2048 + s)) * 3072 + off + h * 128;
        float4 v = *(float4*)&p[lane * 4];
        float ss = v.x * v.x + v.y * v.y + v.z * v.z + v.w * v.w;
#pragma unroll
        for (int o = 16; o; o >>= 1) ss += __shfl_xor_sync(0xffffffffu, ss, o);
        float scl = 1.f / fmaxf(sqrtf(ss), EPS_);
        v.x *= scl; v.y *= scl; v.z *= scl; v.w *= scl;
        float4 u;
        u.x = __shfl_xor_sync(0xffffffffu, v.x, 16);
        u.y = __shfl_xor_sync(0xffffffffu, v.y, 16);
        u.z = __shfl_xor_sync(0xffffffffu, v.z, 16);
        u.w = __shfl_xor_sync(0xffffffffu, v.w, 16);
        bool lohalf = lane < 16;
        int jb = (lane & 15) * 4;
        float ov[4], vv[4] = {v.x, v.y, v.z, v.w}, uu[4] = {u.x, u.y, u.z, u.w};
#pragma unroll
        for (int i = 0; i < 4; i++) {
            float ang = (float)s * g_invf[jb + i];
            float c = cosf(ang), sn = sinf(ang);
            ov[i] = lohalf ? (vv[i] * c + uu[i] * sn) : (-uu[i] * sn + vv[i] * c);
        }
        *(float4*)&p[lane * 4] = make_float4(ov[0], ov[1], ov[2], ov[3]);
    }
}

// ---------------- attention v2 ----------------
__global__ void __launch_bounds__(128) attn2_k(const float* __restrict__ qkv,
                                               const int* __restrict__ doc,
                                               __nv_bfloat16* __restrict__ oh,
                                               __nv_bfloat16* __restrict__ ol) {
    __shared__ __align__(16) float sbuf[8752];
    int qb = blockIdx.x;
    int role = blockIdx.y >> 3;
    int h = blockIdx.y & 7;
    int b = blockIdx.z;
    int t = threadIdx.x;
    int lane = t & 31, w = t >> 5;
    const float* base = qkv + (size_t)b * 2048 * 3072;
    const float* Qb = base + (size_t)h * 128;
    const float* Kb = base + 1024 + (size_t)h * 128;
    const float* Vb = base + 2048 + (size_t)h * 128;
    const float scale = 0.088388347648318447f;

    if (role == 0) {
        float (*qs)[132] = (float(*)[132])sbuf;
        float (*ps)[49]  = (float(*)[49])(sbuf + 6336);
        float* inv = sbuf + 6336 + 2352;
        for (int u = t; u < 48 * 32; u += 128) {
            int rr = u >> 5, c = u & 31;
            *(float4*)&qs[rr][c * 4] =
                *(const float4*)&Qb[(size_t)(qb * 64 + rr) * 3072 + c * 4];
        }
        __syncthreads();
        int tq = t & 15, tk = t >> 4;
        float acc[3][6];
#pragma unroll
        for (int j = 0; j < 3; j++)
#pragma unroll
            for (int i = 0; i < 6; i++) acc[j][i] = 0.f;
#pragma unroll
        for (int dc = 0; dc < 8; dc++) {
            float4 qv[3][4];
#pragma unroll
            for (int j = 0; j < 3; j++)
#pragma unroll
                for (int x = 0; x < 4; x++)
                    qv[j][x] = *(float4*)&qs[tq + 16 * j][dc * 16 + x * 4];
#pragma unroll
            for (int i = 0; i < 6; i++) {
                int k = tk + 8 * i;
                const float4* Kr = (const float4*)&Kb[(size_t)(qb * 64 + k) * 3072 + dc * 16];
#pragma unroll
                for (int x = 0; x < 4; x++) {
                    float4 kv = Kr[x];
#pragma unroll
                    for (int j = 0; j < 3; j++)
                        acc[j][i] += qv[j][x].x * kv.x + qv[j][x].y * kv.y
                                   + qv[j][x].z * kv.z + qv[j][x].w * kv.w;
                }
            }
        }
#pragma unroll
        for (int j = 0; j < 3; j++)
#pragma unroll
            for (int i = 0; i < 6; i++)
                ps[tq + 16 * j][tk + 8 * i] = acc[j][i] * scale;
        __syncthreads();
        for (int j = 0; j < 12; j++) {
            int q = w * 12 + j;
            float v0 = ps[q][lane];
            float v1 = (lane < 16) ? ps[q][lane + 32] : -INFINITY;
            float m = fmaxf(v0, v1);
#pragma unroll
            for (int o = 16; o; o >>= 1) m = fmaxf(m, __shfl_xor_sync(0xffffffffu, m, o));
            float p0 = __expf(v0 - m);
            float p1 = (lane < 16) ? __expf(v1 - m) : 0.f;
            float s = p0 + p1;
#pragma unroll
            for (int o = 16; o; o >>= 1) s += __shfl_xor_sync(0xffffffffu, s, o);
            ps[q][lane] = p0;
            if (lane < 16) ps[q][lane + 32] = p1;
            if (lane == 0) inv[q] = 1.f / s;
        }
        __syncthreads();
        int tq2 = t & 15, td = t >> 4;
        float a2[3][16];
#pragma unroll
        for (int j = 0; j < 3; j++)
#pragma unroll
            for (int x = 0; x < 16; x++) a2[j][x] = 0.f;
        for (int k = 0; k < 48; k++) {
            const float4* Vr = (const float4*)&Vb[(size_t)(qb * 64 + k) * 3072 + td * 16];
            float4 v[4];
#pragma unroll
            for (int x = 0; x < 4; x++) v[x] = Vr[x];
#pragma unroll
            for (int j = 0; j < 3; j++) {
                float p = ps[tq2 + 16 * j][k];
#pragma unroll
                for (int x = 0; x < 4; x++) {
                    a2[j][x * 4 + 0] += p * v[x].x; a2[j][x * 4 + 1] += p * v[x].y;
                    a2[j][x * 4 + 2] += p * v[x].z; a2[j][x * 4 + 3] += p * v[x].w;
                }
            }
        }
#pragma unroll
        for (int j = 0; j < 3; j++) {
            int q = tq2 + 16 * j;
            float iv = inv[q];
            size_t o = ((size_t)(b * 2048 + qb * 64 + q)) * 1024 + h * 128 + td * 16;
#pragma unroll
            for (int x = 0; x < 16; x++) {
                __nv_bfloat16 fh, fl; bsplit(a2[j][x] * iv, fh, fl);
                oh[o + x] = fh; ol[o + x] = fl;
            }
        }
    } else {
        float (*qs)[132] = (float(*)[132])sbuf;
        float (*ps)[324] = (float(*)[324])(sbuf + 2112);
        int*   kls  = (int*)(sbuf + 2112 + 5184);
        int*   docs = kls + 320;
        float* inv  = (float*)(docs + 32);
        int npb = min(16, qb), np = npb * 16, NK = np + 64;
        if (t < 32) docs[t] = doc[b * 32 + t];
        for (int i = t; i < NK; i += 128) {
            int k;
            if (i < np) { int kb = qb - npb + (i >> 4); k = kb * 64 + 48 + (i & 15); }
            else          k = qb * 64 + (i - np);
            kls[i] = k;
        }
        for (int u = t; u < 16 * 32; u += 128) {
            int rr = u >> 5, c = u & 31;
            *(float4*)&qs[rr][c * 4] =
                *(const float4*)&Qb[(size_t)(qb * 64 + 48 + rr) * 3072 + c * 4];
        }
        __syncthreads();
        int tq = t & 15, tk = t >> 4;
#pragma unroll
        for (int dc = 0; dc < 4; dc++) {
            float4 qv[8];
#pragma unroll
            for (int x = 0; x < 8; x++) qv[x] = *(float4*)&qs[tq][dc * 32 + x * 4];
            for (int ki = tk; ki < NK; ki += 8) {
                const float4* Kr = (const float4*)&Kb[(size_t)kls[ki] * 3072 + dc * 32];
                float a = 0.f;
#pragma unroll
                for (int x = 0; x < 8; x++) {
                    float4 kv = Kr[x];
                    a += qv[x].x * kv.x + qv[x].y * kv.y + qv[x].z * kv.z + qv[x].w * kv.w;
                }
                if (dc == 0) ps[tq][ki] = a; else ps[tq][ki] += a;
            }
        }
        {
            int docq = docs[qb];
            int docp = docs[qb > 0 ? qb - 1 : 0];
            int q = qb * 64 + 48 + tq;
            int posq = (48 + tq) + qb * 16;
            for (int ki = tk; ki < NK; ki += 8) {
                int k = kls[ki];
                int kb = k >> 6, kr = k & 63;
                bool newk = kr >= 48;
                int posk = kr + kb * 16;
                bool nn = newk && (q >= k) && (posq < posk + 256) && (docq == docs[kb]);
                bool ao = (!newk) && (kb == qb) && (docq == docp);
                ps[tq][ki] = (nn || ao) ? ps[tq][ki] * scale : -INFINITY;
            }
        }
        __syncthreads();
        for (int j = 0; j < 4; j++) {
            int q = w * 4 + j;
            float m = -INFINITY;
            for (int i = lane; i < NK; i += 32) m = fmaxf(m, ps[q][i]);
#pragma unroll
            for (int o = 16; o; o >>= 1) m = fmaxf(m, __shfl_xor_sync(0xffffffffu, m, o));
            float s = 0.f;
            for (int i = lane; i < NK; i += 32) {
                float v = ps[q][i];
                float p = (v > -INFINITY) ? __expf(v - m) : 0.f;
                ps[q][i] = p;
                s += p;
            }
#pragma unroll
            for (int o = 16; o; o >>= 1) s += __shfl_xor_sync(0xffffffffu, s, o);
            if (lane == 0) inv[q] = 1.f / s;
        }
        __syncthreads();
        int tq3 = t >> 3, td = t & 7;
        float a2[16];
#pragma unroll
        for (int x = 0; x < 16; x++) a2[x] = 0.f;
        for (int ki = 0; ki < NK; ki++) {
            float p = ps[tq3][ki];
            if (p != 0.f) {
                const float4* Vr = (const float4*)&Vb[(size_t)kls[ki] * 3072 + td * 16];
#pragma unroll
                for (int x = 0; x < 4; x++) {
                    float4 v = Vr[x];
                    a2[x * 4 + 0] += p * v.x; a2[x * 4 + 1] += p * v.y;
                    a2[x * 4 + 2] += p * v.z; a2[x * 4 + 3] += p * v.w;
                }
            }
        }
        float iv = inv[tq3];
        size_t o = ((size_t)(b * 2048 + qb * 64 + 48 + tq3)) * 1024 + h * 128 + td * 16;
#pragma unroll
        for (int x = 0; x < 16; x++) {
            __nv_bfloat16 fh, fl; bsplit(a2[x] * iv, fh, fl);
            oh[o + x] = fh; ol[o + x] = fl;
        }
    }
}

// ---------------- assemble x from x_old / (xnew + xnew2 [+ xnew3]) ----------------
__global__ void assemble_k(float* __restrict__ x, const float* __restrict__ xold,
                           const float* __restrict__ xnew, const float* __restrict__ xnew2,
                           const float* __restrict__ xnew3, int nz) {
    int idx = blockIdx.x * blockDim.x + threadIdx.x;
    if (idx >= BP_ * S_ * 256) return;
    int d4 = idx & 255;
    int gr = idx >> 8;
    int b = gr >> 11, s = gr & 2047;
    int l = s >> 6, rr = s & 63;
    float4 v;
    if (rr < 48) {
        v = ((const float4*)xold)[((size_t)((b * 32 + l) * 48 + rr)) * 256 + d4];
    } else {
        size_t o = ((size_t)((b * 32 + l) * 16 + (rr - 48))) * 256 + d4;
        float4 a = ((const float4*)xnew)[o];
        float4 c = ((const float4*)xnew2)[o];
        v = make_float4(a.x + c.x, a.y + c.y, a.z + c.z, a.w + c.w);
        if (nz == 3) {
            float4 e = ((const float4*)xnew3)[o];
            v.x += e.x; v.y += e.y; v.z += e.z; v.w += e.w;
        }
    }
    ((float4*)x)[idx] = v;
}

// ---------------- out = p0 + p1 (final split-K reduction) ----------------
__global__ void add_out_k(const float* __restrict__ p0, const float* __restrict__ p1,
                          float* __restrict__ out) {
    int i = blockIdx.x * 256 + threadIdx.x;   // over (1024*1024)/4 float4s
    if (i >= (1024 * 1024) / 4) return;
    float4 a = ((const float4*)p0)[i];
    float4 c = ((const float4*)p1)[i];
    ((float4*)out)[i] = make_float4(a.x + c.x, a.y + c.y, a.z + c.z, a.w + c.w);
}

// ---------------- extract y (fp32 + split) ----------------
__global__ void extract_y_k(const float* __restrict__ x, float* __restrict__ y,
                            __nv_bfloat16* __restrict__ yh, __nv_bfloat16* __restrict__ yl) {
    int idx = blockIdx.x * blockDim.x + threadIdx.x;
    if (idx >= BP_ * 512 * 256) return;
    int d4 = idx & 255;
    int r = idx >> 8;
    int b = r >> 9, t = r & 511;
    int l = t >> 4, n = t & 15;
    int xr = b * 2048 + l * 64 + 48 + n;
    float4 v = ((const float4*)x)[(size_t)xr * 256 + d4];
    ((float4*)y)[idx] = v;
    __nv_bfloat16 h0, h1, h2, h3, l0, l1, l2, l3;
    bsplit(v.x, h0, l0); bsplit(v.y, h1, l1); bsplit(v.z, h2, l2); bsplit(v.w, h3, l3);
    ((__nv_bfloat162*)yh)[2 * idx]     = __nv_bfloat162(h0, h1);
    ((__nv_bfloat162*)yh)[2 * idx + 1] = __nv_bfloat162(h2, h3);
    ((__nv_bfloat162*)yl)[2 * idx]     = __nv_bfloat162(l0, l1);
    ((__nv_bfloat162*)yl)[2 * idx + 1] = __nv_bfloat162(l2, l3);
}

// ---------------- host helpers ----------------
#define TG_SMEM (3 * 32768)

static void tgemm_z(const __nv_bfloat16* Ah, const __nv_bfloat16* Al,
                    const __nv_bfloat16* Bh, const __nv_bfloat16* Bl,
                    float* C, float* C2, float* C3, __nv_bfloat16* Ch, __nv_bfloat16* Cl,
                    int M, int N, int K, int lda, int ldb, int mode, int nz) {
    dim3 grid(N >> 7, M >> 7, nz);
    if (mode == 0) {
        cudaFuncSetAttribute(tgemm_k<0>, cudaFuncAttributeMaxDynamicSharedMemorySize, TG_SMEM);
        tgemm_k<0><<<grid, 128, TG_SMEM>>>(Ah, Al, Bh, Bl, C, C2, C3, Ch, Cl, M, N, K, lda, ldb);
    } else if (mode == 1) {
        cudaFuncSetAttribute(tgemm_k<1>, cudaFuncAttributeMaxDynamicSharedMemorySize, TG_SMEM);
        tgemm_k<1><<<grid, 128, TG_SMEM>>>(Ah, Al, Bh, Bl, C, C2, C3, Ch, Cl, M, N, K, lda, ldb);
    } else if (mode == 2) {
        cudaFuncSetAttribute(tgemm_k<2>, cudaFuncAttributeMaxDynamicSharedMemorySize, TG_SMEM);
        tgemm_k<2><<<grid, 128, TG_SMEM>>>(Ah, Al, Bh, Bl, C, C2, C3, Ch, Cl, M, N, K, lda, ldb);
    } else {
        cudaFuncSetAttribute(tgemm_k<3>, cudaFuncAttributeMaxDynamicSharedMemorySize, TG_SMEM);
        tgemm_k<3><<<grid, 128, TG_SMEM>>>(Ah, Al, Bh, Bl, C, C2, C3, Ch, Cl, M, N, K, lda, ldb);
    }
}

static void tgemm(const __nv_bfloat16* Ah, const __nv_bfloat16* Al,
                  const __nv_bfloat16* Bh, const __nv_bfloat16* Bl,
                  float* C, __nv_bfloat16* Ch, __nv_bfloat16* Cl,
                  int M, int N, int K, int lda, int ldb, int mode) {
    tgemm_z(Ah, Al, Bh, Bl, C, 0, 0, Ch, Cl, M, N, K, lda, ldb, mode, 1);
}

extern "C" void kernel_launch(void* const* d_in, const int* in_sizes, int n_in,
                              void* d_out, int out_size) {
    (void)in_sizes; (void)n_in; (void)out_size;
    const float* x_input     = (const float*)d_in[0];
    const float* x_ar        = (const float*)d_in[1];
    const int*   doc         = (const int*)d_in[2];
    const int*   begin       = (const int*)d_in[3];
    const float* old_norm_w  = (const float*)d_in[4];
    const float* new_norm_w  = (const float*)d_in[5];
    const float* pad_emb     = (const float*)d_in[12];
    const float* attn_norm_w = (const float*)d_in[14];
    const float* ffn_norm_w  = (const float*)d_in[15];
    float* out = (float*)d_out;

    float *x, *qkv, *xold, *xnew, *xnew2, *xnew3, *y;
    __nv_bfloat16 *hh, *hl, *ah, *al, *gh, *gl;
    __nv_bfloat16 *ach, *acl, *yh, *yl, *whi, *wlo;
    cudaGetSymbolAddress((void**)&x,    g_x);
    cudaGetSymbolAddress((void**)&qkv,  g_qkv);
    cudaGetSymbolAddress((void**)&xold, g_xold);
    cudaGetSymbolAddress((void**)&xnew, g_xnew);
    cudaGetSymbolAddress((void**)&xnew2, g_xnew2);
    cudaGetSymbolAddress((void**)&xnew3, g_xnew3);
    cudaGetSymbolAddress((void**)&y,    g_y);
    cudaGetSymbolAddress((void**)&hh,   g_hh);
    cudaGetSymbolAddress((void**)&hl,   g_hl);
    cudaGetSymbolAddress((void**)&ah,   g_ah);
    cudaGetSymbolAddress((void**)&al,   g_al);
    cudaGetSymbolAddress((void**)&gh,   g_gh);
    cudaGetSymbolAddress((void**)&gl,   g_gl);
    cudaGetSymbolAddress((void**)&ach,  g_ach);
    cudaGetSymbolAddress((void**)&acl,  g_acl);
    cudaGetSymbolAddress((void**)&yh,   g_yh);
    cudaGetSymbolAddress((void**)&yl,   g_yl);
    cudaGetSymbolAddress((void**)&whi,  g_whi);
    cudaGetSymbolAddress((void**)&wlo,  g_wlo);

    init_invf_k<<<1, 64>>>();

    WSrc ws;
    ws.p[0]  = (const float*)d_in[6];
    ws.p[1]  = (const float*)d_in[13];
    ws.p[2]  = (const float*)d_in[16];
    ws.p[3]  = (const float*)d_in[17];
    ws.p[4]  = (const float*)d_in[18];
    ws.p[5]  = (const float*)d_in[19];
    ws.p[6]  = (const float*)d_in[7];
    ws.p[7]  = (const float*)d_in[8];
    ws.p[8]  = (const float*)d_in[9];
    ws.p[9]  = (const float*)d_in[10];
    ws.p[10] = (const float*)d_in[11];
    wsplit_all_k<<<dim3(64, 27), 256>>>(ws, whi, wlo);

    // input projections
    rmsnorm_k<<<3072, 256>>>(x_input, old_norm_w, hh, hl, 48, 64, 0, 1024, 0);
    tgemm(hh, hl, whi + (size_t)OFF_WOLD * MB1, wlo + (size_t)OFF_WOLD * MB1,
          xold, 0, 0, 3072, 1024, 1024, 1024, 1024, 0);
    rmsnorm_k<<<1024, 256>>>(x_ar,    new_norm_w, ach, acl, 16, 16, 0,  3072, 0);
    rmsnorm_k<<<1024, 256>>>(x_input, new_norm_w, ach, acl, 16, 64, 48, 3072, 1024);
    // xnew(+xnew2) = [xarn|xden] @ [w_ar|w_de]^T, split-K=2 (2x1024)
    tgemm_z(ach, acl, whi + (size_t)OFF_WP2 * MB1, wlo + (size_t)OFF_WP2 * MB1,
            xnew, xnew2, 0, 0, 0, 1024, 1024, 1024, 3072, 2048, 0, 2);
    assemble_k<<<(BP_ * S_ * 256 + 255) / 256, 256>>>(x, xold, xnew, xnew2, xnew3, 2);

    for (int it = 0; it < 2; it++) {
        for (int li = 0; li < 2; li++) {
            const __nv_bfloat16* wq_h = whi + (size_t)(OFF_WQKV + 3 * li) * MB1;
            const __nv_bfloat16* wq_l = wlo + (size_t)(OFF_WQKV + 3 * li) * MB1;
            const __nv_bfloat16* wo_h = whi + (size_t)(OFF_WO + li) * MB1;
            const __nv_bfloat16* wo_l = wlo + (size_t)(OFF_WO + li) * MB1;
            const __nv_bfloat16* wu_h = whi + (size_t)(OFF_WUP + 4 * li) * MB1;
            const __nv_bfloat16* wu_l = wlo + (size_t)(OFF_WUP + 4 * li) * MB1;
            const __nv_bfloat16* wd_h = whi + (size_t)(OFF_WDOWN + 2 * li) * MB1;
            const __nv_bfloat16* wd_l = wlo + (size_t)(OFF_WDOWN + 2 * li) * MB1;

            rmsnorm_k<<<4096, 256>>>(x, attn_norm_w + li * 1024, hh, hl, 1, 1, 0, 1024, 0);
            tgemm(hh, hl, wq_h, wq_l, qkv, 0, 0, 4096, 3072, 1024, 1024, 1024, 0);
            qk_rope_k<<<dim3(2048, 2), 256>>>(qkv);
            attn2_k<<<dim3(32, 16, 2), 128>>>(qkv, doc, ah, al);
            tgemm(ah, al, wo_h, wo_l, x, 0, 0, 4096, 1024, 1024, 1024, 1024, 1);
            rmsnorm_k<<<4096, 256>>>(x, ffn_norm_w + li * 1024, hh, hl, 1, 1, 0, 1024, 0);
            tgemm(hh, hl, wu_h, wu_l, 0, gh, gl, 4096, 4096, 1024, 1024, 1024, 3);
            tgemm(gh, gl, wd_h, wd_l, x, 0, 0, 4096, 1024, 2048, 2048, 2048, 1);
        }
        extract_y_k<<<(BP_ * 512 * 256 + 255) / 256, 256>>>(x, y, yh, yl);
        if (it == 0) {
            yfrms_k<<<1024, 256>>>(y, begin, pad_emb, new_norm_w, ach, acl);
            // xnew(+xnew2+xnew3) = [xarn|xden|y2] @ [w_ar1|w_de1|w_y1]^T, split-K=3 (3x1024)
            tgemm_z(ach, acl, whi + (size_t)OFF_WP3 * MB1, wlo + (size_t)OFF_WP3 * MB1,
                    xnew, xnew2, xnew3, 0, 0, 1024, 1024, 1024, 3072, 3072, 0, 3);
            assemble_k<<<(BP_ * S_ * 256 + 255) / 256, 256>>>(x, xold, xnew, xnew2, xnew3, 3);
        }
    }

    // final: out = y @ w_agg^T, split-K=2 (2x512) then reduce
    tgemm_z(yh, yl, whi + (size_t)OFF_WAGG * MB1, wlo + (size_t)OFF_WAGG * MB1,
            xnew, xnew2, 0, 0, 0, 1024, 1024, 512, 1024, 1024, 0, 2);
    add_out_k<<<(1024 * 1024 / 4 + 255) / 256, 256>>>(xnew, xnew2, out);
}

// round 17
// speedup vs baseline: 1.0422x; 1.0422x over previous
#include <cuda_runtime.h>
#include <cuda_bf16.h>
#include <math.h>
#include <stdint.h>

// ---------------- problem constants ----------------
#define BP_  2
#define L_   32
#define N_   16
#define O_   64
#define D_   1024
#define AD_  1024
#define HEAD_ 128
#define W_   256
#define FH_  2048
#define M_   48
#define E_   64
#define S_   2048
#define EPS_ 1e-5f
#define MB1 (1u<<20)

// ---------------- device scratch (allocation-free) ----------------
__device__ float g_x   [BP_ * S_ * AD_];
__device__ float g_qkv [BP_ * S_ * 3 * AD_];
__device__ float g_xold[BP_ * L_ * M_ * AD_];
__device__ float g_xnew[BP_ * L_ * N_ * AD_];
__device__ float g_xnew2[BP_ * L_ * N_ * AD_];   // split-K partial
__device__ float g_y   [BP_ * L_ * N_ * AD_];
__device__ float g_invf[64];

__device__ __nv_bfloat16 g_hh[BP_ * S_ * AD_],  g_hl[BP_ * S_ * AD_];
__device__ __nv_bfloat16 g_ah[BP_ * S_ * AD_],  g_al[BP_ * S_ * AD_];
__device__ __nv_bfloat16 g_gh[BP_ * S_ * FH_],  g_gl[BP_ * S_ * FH_];
__device__ __nv_bfloat16 g_ach[3u * MB1], g_acl[3u * MB1];
__device__ __nv_bfloat16 g_yh[MB1],    g_yl[MB1];
__device__ __nv_bfloat16 g_whi[27u * MB1], g_wlo[27u * MB1];

#define OFF_WOLD  0
#define OFF_WAGG  1
#define OFF_WQKV  2
#define OFF_WO    8
#define OFF_WUP   10  /* rows INTERLEAVED (a,b pairs) */
#define OFF_WDOWN 18
#define OFF_WP2   22
#define OFF_WP3   24

// ---------------- small helpers ----------------
__device__ __forceinline__ void bsplit(float f, __nv_bfloat16& h, __nv_bfloat16& l) {
    h = __float2bfloat16(f);
    l = __float2bfloat16(f - __bfloat162float(h));
}

__device__ __forceinline__ float blk_sum(float v, float* red) {
    int lane = threadIdx.x & 31, w = threadIdx.x >> 5;
#pragma unroll
    for (int o = 16; o; o >>= 1) v += __shfl_xor_sync(0xffffffffu, v, o);
    if (lane == 0) red[w] = v;
    __syncthreads();
    int nw = (blockDim.x + 31) >> 5;
    if (threadIdx.x < 32) {
        float r = (threadIdx.x < nw) ? red[threadIdx.x] : 0.f;
#pragma unroll
        for (int o = 16; o; o >>= 1) r += __shfl_xor_sync(0xffffffffu, r, o);
        if (lane == 0) red[0] = r;
    }
    __syncthreads();
    float r = red[0];
    __syncthreads();
    return r;
}

// ---------------- PTX helpers ----------------
#define SWZ64(o) ((o) ^ (((o) >> 3) & 0x30))

static __device__ __forceinline__ uint32_t smem_u32(const void* p) {
    uint32_t a;
    asm("{ .reg .u64 t; cvta.to.shared.u64 t, %1; cvt.u32.u64 %0, t; }" : "=r"(a) : "l"(p));
    return a;
}
static __device__ __forceinline__ void cpa16(uint32_t dst, const void* src) {
    asm volatile("cp.async.cg.shared.global [%0], [%1], 16;" :: "r"(dst), "l"(src) : "memory");
}
static __device__ __forceinline__ void ldm4(uint32_t& r0, uint32_t& r1, uint32_t& r2,
                                            uint32_t& r3, uint32_t addr) {
    asm volatile("ldmatrix.sync.aligned.m8n8.x4.shared.b16 {%0,%1,%2,%3}, [%4];"
                 : "=r"(r0), "=r"(r1), "=r"(r2), "=r"(r3) : "r"(addr));
}
#define MMA16816(d, a, b) \
    asm volatile("mma.sync.aligned.m16n8k16.row.col.f32.bf16.bf16.f32 " \
        "{%0,%1,%2,%3}, {%4,%5,%6,%7}, {%8,%9}, {%0,%1,%2,%3};" \
        : "+f"((d)[0]), "+f"((d)[1]), "+f"((d)[2]), "+f"((d)[3]) \
        : "r"((a)[0]), "r"((a)[1]), "r"((a)[2]), "r"((a)[3]), "r"((b)[0]), "r"((b)[1]))

// ---------------- tensor-core split-bf16 GEMM (R11/R13 schedule) ----------------
// gridDim.z = split-K count: z picks K-slice [z*K, (z+1)*K); z==1 writes C2.
// OMODE: 0 store fp32, 1 accumulate fp32, 2 store split bf16, 3 fused silu-gate.
template<int OMODE>
__global__ void __launch_bounds__(128, 2) tgemm_k(
    const __nv_bfloat16* __restrict__ Ah, const __nv_bfloat16* __restrict__ Al,
    const __nv_bfloat16* __restrict__ Bh, const __nv_bfloat16* __restrict__ Bl,
    float* __restrict__ C, float* __restrict__ C2,
    __nv_bfloat16* __restrict__ Ch, __nv_bfloat16* __restrict__ Cl,
    int M, int N, int K, int lda, int ldb)
{
    extern __shared__ char smem[];
    uint32_t sb = smem_u32(smem);
    int tid = threadIdx.x, lane = tid & 31, wid = tid >> 5;
    int wm = wid & 1, wn = wid >> 1;
    int brow = blockIdx.y << 7, bcol = blockIdx.x << 7;
    int koff = blockIdx.z * K;
    if (blockIdx.z == 1) C = C2;

    const __nv_bfloat16* src0 = Ah + (size_t)brow * lda + koff;
    const __nv_bfloat16* src1 = Al + (size_t)brow * lda + koff;
    const __nv_bfloat16* src2 = Bh + (size_t)bcol * ldb + koff;
    const __nv_bfloat16* src3 = Bl + (size_t)bcol * ldb + koff;

    float d[4][8][4];
#pragma unroll
    for (int mi = 0; mi < 4; mi++)
#pragma unroll
        for (int ni = 0; ni < 8; ni++)
#pragma unroll
            for (int q = 0; q < 4; q++) d[mi][ni][q] = 0.f;

    const int nch = K >> 5;

    auto load_stage = [&](uint32_t stb, int k0) {
#pragma unroll
        for (int j = 0; j < 4; j++) {
            int u = tid + (j << 7);
            int row = u >> 2, un = u & 3;
            uint32_t doff = SWZ64((uint32_t)(row * 64 + un * 16));
            size_t ga = (size_t)row * lda + k0 + un * 8;
            size_t gb = (size_t)row * ldb + k0 + un * 8;
            cpa16(stb +     0 + doff, src0 + ga);
            cpa16(stb +  8192 + doff, src1 + ga);
            cpa16(stb + 16384 + doff, src2 + gb);
            cpa16(stb + 24576 + doff, src3 + gb);
        }
        asm volatile("cp.async.commit_group;" ::: "memory");
    };

    load_stage(sb, 0);
    if (nch > 1) load_stage(sb + 32768, 32);

    int g = lane >> 3, r = lane & 7;
    for (int i = 0; i < nch; i++) {
        if (i + 1 < nch) { asm volatile("cp.async.wait_group 1;" ::: "memory"); }
        else             { asm volatile("cp.async.wait_group 0;" ::: "memory"); }
        __syncthreads();
        if (i + 2 < nch) {
            int s = (i + 2) % 3;
            load_stage(sb + (uint32_t)(s * 32768), (i + 2) << 5);
        }
        uint32_t stb = sb + (uint32_t)((i % 3) * 32768);

#pragma unroll
        for (int ks = 0; ks < 2; ks++) {
            uint32_t ah[4][4], al[4][4], bh[8][2], bl[8][2];
#pragma unroll
            for (int mi = 0; mi < 4; mi++) {
                int row = wm * 64 + mi * 16 + (g & 1) * 8 + r;
                int colb = ks * 32 + (g >> 1) * 16;
                uint32_t off = SWZ64((uint32_t)(row * 64 + colb));
                ldm4(ah[mi][0], ah[mi][1], ah[mi][2], ah[mi][3], stb + off);
                ldm4(al[mi][0], al[mi][1], al[mi][2], al[mi][3], stb + 8192 + off);
            }
#pragma unroll
            for (int n2 = 0; n2 < 4; n2++) {
                int rown = wn * 64 + n2 * 16 + (g >> 1) * 8 + r;
                int colb = ks * 32 + (g & 1) * 16;
                uint32_t off = SWZ64((uint32_t)(rown * 64 + colb));
                ldm4(bh[2*n2][0], bh[2*n2][1], bh[2*n2+1][0], bh[2*n2+1][1], stb + 16384 + off);
                ldm4(bl[2*n2][0], bl[2*n2][1], bl[2*n2+1][0], bl[2*n2+1][1], stb + 24576 + off);
            }
#pragma unroll
            for (int mi = 0; mi < 4; mi++)
#pragma unroll
                for (int ni = 0; ni < 8; ni++) MMA16816(d[mi][ni], ah[mi], bh[ni]);
#pragma unroll
            for (int mi = 0; mi < 4; mi++)
#pragma unroll
                for (int ni = 0; ni < 8; ni++) MMA16816(d[mi][ni], ah[mi], bl[ni]);
#pragma unroll
            for (int mi = 0; mi < 4; mi++)
#pragma unroll
                for (int ni = 0; ni < 8; ni++) MMA16816(d[mi][ni], al[mi], bh[ni]);
        }
    }

    // epilogue
#pragma unroll
    for (int mi = 0; mi < 4; mi++)
#pragma unroll
        for (int ni = 0; ni < 8; ni++) {
            int row = brow + wm * 64 + mi * 16 + (lane >> 2);
            int col = bcol + wn * 64 + ni * 8 + 2 * (lane & 3);
            if (OMODE == 3) {
                int gcol = col >> 1;
                int gn = N >> 1;
                float a0 = d[mi][ni][0], b0 = d[mi][ni][1];
                float a1 = d[mi][ni][2], b1 = d[mi][ni][3];
                float f0 = (a0 / (1.f + __expf(-a0))) * b0;
                float f1 = (a1 / (1.f + __expf(-a1))) * b1;
                __nv_bfloat16 h0, l0, h1, l1;
                bsplit(f0, h0, l0); bsplit(f1, h1, l1);
                Ch[(size_t)row * gn + gcol] = h0;
                Cl[(size_t)row * gn + gcol] = l0;
                Ch[(size_t)(row + 8) * gn + gcol] = h1;
                Cl[(size_t)(row + 8) * gn + gcol] = l1;
            } else if (OMODE == 2) {
                __nv_bfloat16 h0, h1, l0, l1;
                bsplit(d[mi][ni][0], h0, l0); bsplit(d[mi][ni][1], h1, l1);
                *(__nv_bfloat162*)(Ch + (size_t)row * N + col) = __nv_bfloat162(h0, h1);
                *(__nv_bfloat162*)(Cl + (size_t)row * N + col) = __nv_bfloat162(l0, l1);
                bsplit(d[mi][ni][2], h0, l0); bsplit(d[mi][ni][3], h1, l1);
                *(__nv_bfloat162*)(Ch + (size_t)(row + 8) * N + col) = __nv_bfloat162(h0, h1);
                *(__nv_bfloat162*)(Cl + (size_t)(row + 8) * N + col) = __nv_bfloat162(l0, l1);
            } else {
                float* p0 = C + (size_t)row * N + col;
                float* p1 = C + (size_t)(row + 8) * N + col;
                float2 v0 = make_float2(d[mi][ni][0], d[mi][ni][1]);
                float2 v1 = make_float2(d[mi][ni][2], d[mi][ni][3]);
                if (OMODE == 1) {
                    float2 o0 = *(const float2*)p0, o1 = *(const float2*)p1;
                    v0.x += o0.x; v0.y += o0.y; v1.x += o1.x; v1.y += o1.y;
                }
                *(float2*)p0 = v0;
                *(float2*)p1 = v1;
            }
        }
}

// ---------------- fused weight split (also builds inv_freq table) ----------------
struct WSrc { const float* p[11]; };
__global__ void wsplit_all_k(WSrc ws, __nv_bfloat16* __restrict__ hi,
                             __nv_bfloat16* __restrict__ lo) {
    const unsigned char segOf[27] = {0,1, 2,2,2,2,2,2, 3,3, 4,4,4,4,4,4,4,4, 5,5,5,5, 6,7, 8,9,10};
    const unsigned char locOf[27] = {0,0, 0,1,2,3,4,5, 0,1, 0,1,2,3,4,5,6,7, 0,1,2,3, 0,0, 0,0,0};
    const unsigned char baseOf[27]= {0,1, 2,3,4,5,6,7, 8,9, 10,11,12,13,14,15,16,17, 18,19,20,21, 22,22, 24,24,24};
    const unsigned short strOf[27]= {1024,1024, 1024,1024,1024,1024,1024,1024, 1024,1024,
                                     1024,1024,1024,1024,1024,1024,1024,1024, 1024,1024,1024,1024,
                                     2048,2048, 3072,3072,3072};
    const unsigned short colOf[27]= {0,0, 0,0,0,0,0,0, 0,0, 0,0,0,0,0,0,0,0, 0,0,0,0,
                                     0,1024, 0,1024,2048};
    if (blockIdx.y == 0 && blockIdx.x == 0 && threadIdx.x < 64) {
        double invf_d = exp(-(double)threadIdx.x * (9.210340371976184 / 64.0));
        g_invf[threadIdx.x] = (float)invf_d;
    }
    int unit = blockIdx.y;
    bool ileave = (unit >= 10 && unit <= 17);
    const float4* src = (const float4*)ws.p[segOf[unit]] + (size_t)locOf[unit] * (MB1 >> 2);
    for (int i = blockIdx.x * blockDim.x + threadIdx.x; i < (int)(MB1 >> 2);
         i += gridDim.x * blockDim.x) {
        float4 v = src[i];
        int row = i >> 8, c4 = i & 255;
        size_t e;
        if (ileave) {
            int layer = (unit - 10) >> 2, loc = (unit - 10) & 3;
            int grow = loc * 1024 + row;
            int drow = (grow < 2048) ? (grow * 2) : ((grow - 2048) * 2 + 1);
            e = (size_t)(OFF_WUP + 4 * layer) * MB1 + (size_t)drow * 1024 + c4 * 4;
        } else {
            e = (size_t)baseOf[unit] * MB1 + (size_t)row * strOf[unit] + colOf[unit] + c4 * 4;
        }
        __nv_bfloat16 h0, h1, h2, h3, l0, l1, l2, l3;
        bsplit(v.x, h0, l0); bsplit(v.y, h1, l1);
        bsplit(v.z, h2, l2); bsplit(v.w, h3, l3);
        *(__nv_bfloat162*)(hi + e)     = __nv_bfloat162(h0, h1);
        *(__nv_bfloat162*)(hi + e + 2) = __nv_bfloat162(h2, h3);
        *(__nv_bfloat162*)(lo + e)     = __nv_bfloat162(l0, l1);
        *(__nv_bfloat162*)(lo + e + 2) = __nv_bfloat162(l2, l3);
    }
}

// ---------------- rmsnorm -> split bf16 ----------------
__global__ void rmsnorm_k(const float* __restrict__ in, const float* __restrict__ w,
                          __nv_bfloat16* __restrict__ oh, __nv_bfloat16* __restrict__ ol,
                          int gsize, int gstride, int goff, int ostride, int ooff) {
    __shared__ float red[32];
    int r = blockIdx.x;
    int inrow = (r / gsize) * gstride + goff + (r % gsize);
    float4 v = ((const float4*)(in + (size_t)inrow * 1024))[threadIdx.x];
    float ss = v.x * v.x + v.y * v.y + v.z * v.z + v.w * v.w;
    ss = blk_sum(ss, red);
    float sc = rsqrtf(ss * (1.f / 1024.f) + EPS_);
    float4 wv = ((const float4*)w)[threadIdx.x];
    __nv_bfloat16 h0, h1, h2, h3, l0, l1, l2, l3;
    bsplit(v.x * sc * wv.x, h0, l0); bsplit(v.y * sc * wv.y, h1, l1);
    bsplit(v.z * sc * wv.z, h2, l2); bsplit(v.w * sc * wv.w, h3, l3);
    size_t o = (size_t)r * ostride + ooff + threadIdx.x * 4;
    *(__nv_bfloat162*)(oh + o)     = __nv_bfloat162(h0, h1);
    *(__nv_bfloat162*)(oh + o + 2) = __nv_bfloat162(h2, h3);
    *(__nv_bfloat162*)(ol + o)     = __nv_bfloat162(l0, l1);
    *(__nv_bfloat162*)(ol + o + 2) = __nv_bfloat162(l2, l3);
}

// ---------------- fused shifted-y + rmsnorm -> ach cols 2048..3071 ----------------
__global__ void yfrms_k(const float* __restrict__ y, const int* __restrict__ begin,
                        const float* __restrict__ pad_emb, const float* __restrict__ w,
                        __nv_bfloat16* __restrict__ oh, __nv_bfloat16* __restrict__ ol) {
    __shared__ float red[32];
    int r = blockIdx.x;
    int b = r >> 9, t = r & 511;
    int n = t & 15, l = t >> 4;
    bool cond = (n == 0) && (begin[b * 32 + l] != 0);
    const float* x = cond ? pad_emb : (y + ((size_t)b * 512 + ((t + 511) & 511)) * 1024);
    float4 v = ((const float4*)x)[threadIdx.x];
    float ss = v.x * v.x + v.y * v.y + v.z * v.z + v.w * v.w;
    ss = blk_sum(ss, red);
    float sc = rsqrtf(ss * (1.f / 1024.f) + EPS_);
    float4 wv = ((const float4*)w)[threadIdx.x];
    __nv_bfloat16 h0, h1, h2, h3, l0, l1, l2, l3;
    bsplit(v.x * sc * wv.x, h0, l0); bsplit(v.y * sc * wv.y, h1, l1);
    bsplit(v.z * sc * wv.z, h2, l2); bsplit(v.w * sc * wv.w, h3, l3);
    size_t o = (size_t)r * 3072 + 2048 + threadIdx.x * 4;
    *(__nv_bfloat162*)(oh + o)     = __nv_bfloat162(h0, h1);
    *(__nv_bfloat162*)(oh + o + 2) = __nv_bfloat162(h2, h3);
    *(__nv_bfloat162*)(ol + o)     = __nv_bfloat162(l0, l1);
    *(__nv_bfloat162*)(ol + o + 2) = __nv_bfloat162(l2, l3);
}

// ---------------- l2norm + rotary ----------------
__global__ void __launch_bounds__(256) qk_rope_k(float* __restrict__ qkv) {
    int s = blockIdx.x, b = blockIdx.y;
    int t = threadIdx.x, w = t >> 5, lane = t & 31;
#pragma unroll
    for (int si = 0; si < 2; si++) {
        int sg = w * 2 + si;
        int h = sg >> 1;
        int off = (sg & 1) ? 1024 : 0;
        float* p = qkv + ((size_t)(b * 2048 + s)) * 3072 + off + h * 128;
        float4 v = *(float4*)&p[lane * 4];
        float ss = v.x * v.x + v.y * v.y + v.z * v.z + v.w * v.w;
#pragma unroll
        for (int o = 16; o; o >>= 1) ss += __shfl_xor_sync(0xffffffffu, ss, o);
        float scl = 1.f / fmaxf(sqrtf(ss), EPS_);
        v.x *= scl; v.y *= scl; v.z *= scl; v.w *= scl;
        float4 u;
        u.x = __shfl_xor_sync(0xffffffffu, v.x, 16);
        u.y = __shfl_xor_sync(0xffffffffu, v.y, 16);
        u.z = __shfl_xor_sync(0xffffffffu, v.z, 16);
        u.w = __shfl_xor_sync(0xffffffffu, v.w, 16);
        bool lohalf = lane < 16;
        int jb = (lane & 15) * 4;
        float ov[4], vv[4] = {v.x, v.y, v.z, v.w}, uu[4] = {u.x, u.y, u.z, u.w};
#pragma unroll
        for (int i = 0; i < 4; i++) {
            float ang = (float)s * g_invf[jb + i];
            float c = cosf(ang), sn = sinf(ang);
            ov[i] = lohalf ? (vv[i] * c + uu[i] * sn) : (-uu[i] * sn + vv[i] * c);
        }
        *(float4*)&p[lane * 4] = make_float4(ov[0], ov[1], ov[2], ov[3]);
    }
}

// ---------------- attention v2 ----------------
__global__ void __launch_bounds__(128) attn2_k(const float* __restrict__ qkv,
                                               const int* __restrict__ doc,
                                               __nv_bfloat16* __restrict__ oh,
                                               __nv_bfloat16* __restrict__ ol) {
    __shared__ __align__(16) float sbuf[8752];
    int qb = blockIdx.x;
    int role = blockIdx.y >> 3;
    int h = blockIdx.y & 7;
    int b = blockIdx.z;
    int t = threadIdx.x;
    int lane = t & 31, w = t >> 5;
    const float* base = qkv + (size_t)b * 2048 * 3072;
    const float* Qb = base + (size_t)h * 128;
    const float* Kb = base + 1024 + (size_t)h * 128;
    const float* Vb = base + 2048 + (size_t)h * 128;
    const float scale = 0.088388347648318447f;

    if (role == 0) {
        float (*qs)[132] = (float(*)[132])sbuf;
        float (*ps)[49]  = (float(*)[49])(sbuf + 6336);
        float* inv = sbuf + 6336 + 2352;
        for (int u = t; u < 48 * 32; u += 128) {
            int rr = u >> 5, c = u & 31;
            *(float4*)&qs[rr][c * 4] =
                *(const float4*)&Qb[(size_t)(qb * 64 + rr) * 3072 + c * 4];
        }
        __syncthreads();
        int tq = t & 15, tk = t >> 4;
        float acc[3][6];
#pragma unroll
        for (int j = 0; j < 3; j++)
#pragma unroll
            for (int i = 0; i < 6; i++) acc[j][i] = 0.f;
#pragma unroll
        for (int dc = 0; dc < 8; dc++) {
            float4 qv[3][4];
#pragma unroll
            for (int j = 0; j < 3; j++)
#pragma unroll
                for (int x = 0; x < 4; x++)
                    qv[j][x] = *(float4*)&qs[tq + 16 * j][dc * 16 + x * 4];
#pragma unroll
            for (int i = 0; i < 6; i++) {
                int k = tk + 8 * i;
                const float4* Kr = (const float4*)&Kb[(size_t)(qb * 64 + k) * 3072 + dc * 16];
#pragma unroll
                for (int x = 0; x < 4; x++) {
                    float4 kv = Kr[x];
#pragma unroll
                    for (int j = 0; j < 3; j++)
                        acc[j][i] += qv[j][x].x * kv.x + qv[j][x].y * kv.y
                                   + qv[j][x].z * kv.z + qv[j][x].w * kv.w;
                }
            }
        }
#pragma unroll
        for (int j = 0; j < 3; j++)
#pragma unroll
            for (int i = 0; i < 6; i++)
                ps[tq + 16 * j][tk + 8 * i] = acc[j][i] * scale;
        __syncthreads();
        for (int j = 0; j < 12; j++) {
            int q = w * 12 + j;
            float v0 = ps[q][lane];
            float v1 = (lane < 16) ? ps[q][lane + 32] : -INFINITY;
            float m = fmaxf(v0, v1);
#pragma unroll
            for (int o = 16; o; o >>= 1) m = fmaxf(m, __shfl_xor_sync(0xffffffffu, m, o));
            float p0 = __expf(v0 - m);
            float p1 = (lane < 16) ? __expf(v1 - m) : 0.f;
            float s = p0 + p1;
#pragma unroll
            for (int o = 16; o; o >>= 1) s += __shfl_xor_sync(0xffffffffu, s, o);
            ps[q][lane] = p0;
            if (lane < 16) ps[q][lane + 32] = p1;
            if (lane == 0) inv[q] = 1.f / s;
        }
        __syncthreads();
        int tq2 = t & 15, td = t >> 4;
        float a2[3][16];
#pragma unroll
        for (int j = 0; j < 3; j++)
#pragma unroll
            for (int x = 0; x < 16; x++) a2[j][x] = 0.f;
        for (int k = 0; k < 48; k++) {
            const float4* Vr = (const float4*)&Vb[(size_t)(qb * 64 + k) * 3072 + td * 16];
            float4 v[4];
#pragma unroll
            for (int x = 0; x < 4; x++) v[x] = Vr[x];
#pragma unroll
            for (int j = 0; j < 3; j++) {
                float p = ps[tq2 + 16 * j][k];
#pragma unroll
                for (int x = 0; x < 4; x++) {
                    a2[j][x * 4 + 0] += p * v[x].x; a2[j][x * 4 + 1] += p * v[x].y;
                    a2[j][x * 4 + 2] += p * v[x].z; a2[j][x * 4 + 3] += p * v[x].w;
                }
            }
        }
#pragma unroll
        for (int j = 0; j < 3; j++) {
            int q = tq2 + 16 * j;
            float iv = inv[q];
            size_t o = ((size_t)(b * 2048 + qb * 64 + q)) * 1024 + h * 128 + td * 16;
#pragma unroll
            for (int x = 0; x < 16; x += 2) {
                __nv_bfloat16 fh0, fl0, fh1, fl1;
                bsplit(a2[j][x] * iv, fh0, fl0);
                bsplit(a2[j][x + 1] * iv, fh1, fl1);
                *(__nv_bfloat162*)(oh + o + x) = __nv_bfloat162(fh0, fh1);
                *(__nv_bfloat162*)(ol + o + x) = __nv_bfloat162(fl0, fl1);
            }
        }
    } else {
        float (*qs)[132] = (float(*)[132])sbuf;
        float (*ps)[324] = (float(*)[324])(sbuf + 2112);
        int*   kls  = (int*)(sbuf + 2112 + 5184);
        int*   docs = kls + 320;
        float* inv  = (float*)(docs + 32);
        int npb = min(16, qb), np = npb * 16, NK = np + 64;
        if (t < 32) docs[t] = doc[b * 32 + t];
        for (int i = t; i < NK; i += 128) {
            int k;
            if (i < np) { int kb = qb - npb + (i >> 4); k = kb * 64 + 48 + (i & 15); }
            else          k = qb * 64 + (i - np);
            kls[i] = k;
        }
        for (int u = t; u < 16 * 32; u += 128) {
            int rr = u >> 5, c = u & 31;
            *(float4*)&qs[rr][c * 4] =
                *(const float4*)&Qb[(size_t)(qb * 64 + 48 + rr) * 3072 + c * 4];
        }
        __syncthreads();
        int tq = t & 15, tk = t >> 4;
#pragma unroll
        for (int dc = 0; dc < 4; dc++) {
            float4 qv[8];
#pragma unroll
            for (int x = 0; x < 8; x++) qv[x] = *(float4*)&qs[tq][dc * 32 + x * 4];
            for (int ki = tk; ki < NK; ki += 8) {
                const float4* Kr = (const float4*)&Kb[(size_t)kls[ki] * 3072 + dc * 32];
                float a = 0.f;
#pragma unroll
                for (int x = 0; x < 8; x++) {
                    float4 kv = Kr[x];
                    a += qv[x].x * kv.x + qv[x].y * kv.y + qv[x].z * kv.z + qv[x].w * kv.w;
                }
                if (dc == 0) ps[tq][ki] = a; else ps[tq][ki] += a;
            }
        }
        {
            int docq = docs[qb];
            int docp = docs[qb > 0 ? qb - 1 : 0];
            int q = qb * 64 + 48 + tq;
            int posq = (48 + tq) + qb * 16;
            for (int ki = tk; ki < NK; ki += 8) {
                int k = kls[ki];
                int kb = k >> 6, kr = k & 63;
                bool newk = kr >= 48;
                int posk = kr + kb * 16;
                bool nn = newk && (q >= k) && (posq < posk + 256) && (docq == docs[kb]);
                bool ao = (!newk) && (kb == qb) && (docq == docp);
                ps[tq][ki] = (nn || ao) ? ps[tq][ki] * scale : -INFINITY;
            }
        }
        __syncthreads();
        for (int j = 0; j < 4; j++) {
            int q = w * 4 + j;
            float m = -INFINITY;
            for (int i = lane; i < NK; i += 32) m = fmaxf(m, ps[q][i]);
#pragma unroll
            for (int o = 16; o; o >>= 1) m = fmaxf(m, __shfl_xor_sync(0xffffffffu, m, o));
            float s = 0.f;
            for (int i = lane; i < NK; i += 32) {
                float v = ps[q][i];
                float p = (v > -INFINITY) ? __expf(v - m) : 0.f;
                ps[q][i] = p;
                s += p;
            }
#pragma unroll
            for (int o = 16; o; o >>= 1) s += __shfl_xor_sync(0xffffffffu, s, o);
            if (lane == 0) inv[q] = 1.f / s;
        }
        __syncthreads();
        int tq3 = t >> 3, td = t & 7;
        float a2[16];
#pragma unroll
        for (int x = 0; x < 16; x++) a2[x] = 0.f;
        for (int ki = 0; ki < NK; ki++) {
            float p = ps[tq3][ki];
            if (p != 0.f) {
                const float4* Vr = (const float4*)&Vb[(size_t)kls[ki] * 3072 + td * 16];
#pragma unroll
                for (int x = 0; x < 4; x++) {
                    float4 v = Vr[x];
                    a2[x * 4 + 0] += p * v.x; a2[x * 4 + 1] += p * v.y;
                    a2[x * 4 + 2] += p * v.z; a2[x * 4 + 3] += p * v.w;
                }
            }
        }
        float iv = inv[tq3];
        size_t o = ((size_t)(b * 2048 + qb * 64 + 48 + tq3)) * 1024 + h * 128 + td * 16;
#pragma unroll
        for (int x = 0; x < 16; x += 2) {
            __nv_bfloat16 fh0, fl0, fh1, fl1;
            bsplit(a2[x] * iv, fh0, fl0);
            bsplit(a2[x + 1] * iv, fh1, fl1);
            *(__nv_bfloat162*)(oh + o + x) = __nv_bfloat162(fh0, fh1);
            *(__nv_bfloat162*)(ol + o + x) = __nv_bfloat162(fl0, fl1);
        }
    }
}

// ---------------- assemble x from x_old / (xnew + xnew2) ----------------
__global__ void assemble_k(float* __restrict__ x, const float* __restrict__ xold,
                           const float* __restrict__ xnew, const float* __restrict__ xnew2) {
    int idx = blockIdx.x * blockDim.x + threadIdx.x;
    if (idx >= BP_ * S_ * 256) return;
    int d4 = idx & 255;
    int gr = idx >> 8;
    int b = gr >> 11, s = gr & 2047;
    int l = s >> 6, rr = s & 63;
    float4 v;
    if (rr < 48) {
        v = ((const float4*)xold)[((size_t)((b * 32 + l) * 48 + rr)) * 256 + d4];
    } else {
        size_t o = ((size_t)((b * 32 + l) * 16 + (rr - 48))) * 256 + d4;
        float4 a = ((const float4*)xnew)[o];
        float4 c = ((const float4*)xnew2)[o];
        v = make_float4(a.x + c.x, a.y + c.y, a.z + c.z, a.w + c.w);
    }
    ((float4*)x)[idx] = v;
}

// ---------------- extract y (fp32 + split) ----------------
__global__ void extract_y_k(const float* __restrict__ x, float* __restrict__ y,
                            __nv_bfloat16* __restrict__ yh, __nv_bfloat16* __restrict__ yl) {
    int idx = blockIdx.x * blockDim.x + threadIdx.x;
    if (idx >= BP_ * 512 * 256) return;
    int d4 = idx & 255;
    int r = idx >> 8;
    int b = r >> 9, t = r & 511;
    int l = t >> 4, n = t & 15;
    int xr = b * 2048 + l * 64 + 48 + n;
    float4 v = ((const float4*)x)[(size_t)xr * 256 + d4];
    ((float4*)y)[idx] = v;
    __nv_bfloat16 h0, h1, h2, h3, l0, l1, l2, l3;
    bsplit(v.x, h0, l0); bsplit(v.y, h1, l1); bsplit(v.z, h2, l2); bsplit(v.w, h3, l3);
    ((__nv_bfloat162*)yh)[2 * idx]     = __nv_bfloat162(h0, h1);
    ((__nv_bfloat162*)yh)[2 * idx + 1] = __nv_bfloat162(h2, h3);
    ((__nv_bfloat162*)yl)[2 * idx]     = __nv_bfloat162(l0, l1);
    ((__nv_bfloat162*)yl)[2 * idx + 1] = __nv_bfloat162(l2, l3);
}

// ---------------- host helpers ----------------
#define TG_SMEM (3 * 32768)

static void tgemm_z(const __nv_bfloat16* Ah, const __nv_bfloat16* Al,
                    const __nv_bfloat16* Bh, const __nv_bfloat16* Bl,
                    float* C, float* C2, __nv_bfloat16* Ch, __nv_bfloat16* Cl,
                    int M, int N, int K, int lda, int ldb, int mode, int nz) {
    dim3 grid(N >> 7, M >> 7, nz);
    if (mode == 0) {
        cudaFuncSetAttribute(tgemm_k<0>, cudaFuncAttributeMaxDynamicSharedMemorySize, TG_SMEM);
        tgemm_k<0><<<grid, 128, TG_SMEM>>>(Ah, Al, Bh, Bl, C, C2, Ch, Cl, M, N, K, lda, ldb);
    } else if (mode == 1) {
        cudaFuncSetAttribute(tgemm_k<1>, cudaFuncAttributeMaxDynamicSharedMemorySize, TG_SMEM);
        tgemm_k<1><<<grid, 128, TG_SMEM>>>(Ah, Al, Bh, Bl, C, C2, Ch, Cl, M, N, K, lda, ldb);
    } else if (mode == 2) {
        cudaFuncSetAttribute(tgemm_k<2>, cudaFuncAttributeMaxDynamicSharedMemorySize, TG_SMEM);
        tgemm_k<2><<<grid, 128, TG_SMEM>>>(Ah, Al, Bh, Bl, C, C2, Ch, Cl, M, N, K, lda, ldb);
    } else {
        cudaFuncSetAttribute(tgemm_k<3>, cudaFuncAttributeMaxDynamicSharedMemorySize, TG_SMEM);
        tgemm_k<3><<<grid, 128, TG_SMEM>>>(Ah, Al, Bh, Bl, C, C2, Ch, Cl, M, N, K, lda, ldb);
    }
}

static void tgemm(const __nv_bfloat16* Ah, const __nv_bfloat16* Al,
                  const __nv_bfloat16* Bh, const __nv_bfloat16* Bl,
                  float* C, __nv_bfloat16* Ch, __nv_bfloat16* Cl,
                  int M, int N, int K, int lda, int ldb, int mode) {
    tgemm_z(Ah, Al, Bh, Bl, C, 0, Ch, Cl, M, N, K, lda, ldb, mode, 1);
}

extern "C" void kernel_launch(void* const* d_in, const int* in_sizes, int n_in,
                              void* d_out, int out_size) {
    (void)in_sizes; (void)n_in; (void)out_size;
    const float* x_input     = (const float*)d_in[0];
    const float* x_ar        = (const float*)d_in[1];
    const int*   doc         = (const int*)d_in[2];
    const int*   begin       = (const int*)d_in[3];
    const float* old_norm_w  = (const float*)d_in[4];
    const float* new_norm_w  = (const float*)d_in[5];
    const float* pad_emb     = (const float*)d_in[12];
    const float* attn_norm_w = (const float*)d_in[14];
    const float* ffn_norm_w  = (const float*)d_in[15];
    float* out = (float*)d_out;

    float *x, *qkv, *xold, *xnew, *xnew2, *y;
    __nv_bfloat16 *hh, *hl, *ah, *al, *gh, *gl;
    __nv_bfloat16 *ach, *acl, *yh, *yl, *whi, *wlo;
    cudaGetSymbolAddress((void**)&x,    g_x);
    cudaGetSymbolAddress((void**)&qkv,  g_qkv);
    cudaGetSymbolAddress((void**)&xold, g_xold);
    cudaGetSymbolAddress((void**)&xnew, g_xnew);
    cudaGetSymbolAddress((void**)&xnew2, g_xnew2);
    cudaGetSymbolAddress((void**)&y,    g_y);
    cudaGetSymbolAddress((void**)&hh,   g_hh);
    cudaGetSymbolAddress((void**)&hl,   g_hl);
    cudaGetSymbolAddress((void**)&ah,   g_ah);
    cudaGetSymbolAddress((void**)&al,   g_al);
    cudaGetSymbolAddress((void**)&gh,   g_gh);
    cudaGetSymbolAddress((void**)&gl,   g_gl);
    cudaGetSymbolAddress((void**)&ach,  g_ach);
    cudaGetSymbolAddress((void**)&acl,  g_acl);
    cudaGetSymbolAddress((void**)&yh,   g_yh);
    cudaGetSymbolAddress((void**)&yl,   g_yl);
    cudaGetSymbolAddress((void**)&whi,  g_whi);
    cudaGetSymbolAddress((void**)&wlo,  g_wlo);

    WSrc ws;
    ws.p[0]  = (const float*)d_in[6];
    ws.p[1]  = (const float*)d_in[13];
    ws.p[2]  = (const float*)d_in[16];
    ws.p[3]  = (const float*)d_in[17];
    ws.p[4]  = (const float*)d_in[18];
    ws.p[5]  = (const float*)d_in[19];
    ws.p[6]  = (const float*)d_in[7];
    ws.p[7]  = (const float*)d_in[8];
    ws.p[8]  = (const float*)d_in[9];
    ws.p[9]  = (const float*)d_in[10];
    ws.p[10] = (const float*)d_in[11];
    wsplit_all_k<<<dim3(64, 27), 256>>>(ws, whi, wlo);

    // input projections
    rmsnorm_k<<<3072, 256>>>(x_input, old_norm_w, hh, hl, 48, 64, 0, 1024, 0);
    tgemm(hh, hl, whi + (size_t)OFF_WOLD * MB1, wlo + (size_t)OFF_WOLD * MB1,
          xold, 0, 0, 3072, 1024, 1024, 1024, 1024, 0);
    rmsnorm_k<<<1024, 256>>>(x_ar,    new_norm_w, ach, acl, 16, 16, 0,  3072, 0);
    rmsnorm_k<<<1024, 256>>>(x_input, new_norm_w, ach, acl, 16, 64, 48, 3072, 1024);
    // xnew(+xnew2) = [xarn|xden] @ [w_ar|w_de]^T, split-K=2 (2x1024)
    tgemm_z(ach, acl, whi + (size_t)OFF_WP2 * MB1, wlo + (size_t)OFF_WP2 * MB1,
            xnew, xnew2, 0, 0, 1024, 1024, 1024, 3072, 2048, 0, 2);
    assemble_k<<<(BP_ * S_ * 256 + 255) / 256, 256>>>(x, xold, xnew, xnew2);

    for (int it = 0; it < 2; it++) {
        for (int li = 0; li < 2; li++) {
            const __nv_bfloat16* wq_h = whi + (size_t)(OFF_WQKV + 3 * li) * MB1;
            const __nv_bfloat16* wq_l = wlo + (size_t)(OFF_WQKV + 3 * li) * MB1;
            const __nv_bfloat16* wo_h = whi + (size_t)(OFF_WO + li) * MB1;
            const __nv_bfloat16* wo_l = wlo + (size_t)(OFF_WO + li) * MB1;
            const __nv_bfloat16* wu_h = whi + (size_t)(OFF_WUP + 4 * li) * MB1;
            const __nv_bfloat16* wu_l = wlo + (size_t)(OFF_WUP + 4 * li) * MB1;
            const __nv_bfloat16* wd_h = whi + (size_t)(OFF_WDOWN + 2 * li) * MB1;
            const __nv_bfloat16* wd_l = wlo + (size_t)(OFF_WDOWN + 2 * li) * MB1;

            rmsnorm_k<<<4096, 256>>>(x, attn_norm_w + li * 1024, hh, hl, 1, 1, 0, 1024, 0);
            tgemm(hh, hl, wq_h, wq_l, qkv, 0, 0, 4096, 3072, 1024, 1024, 1024, 0);
            qk_rope_k<<<dim3(2048, 2), 256>>>(qkv);
            attn2_k<<<dim3(32, 16, 2), 128>>>(qkv, doc, ah, al);
            tgemm(ah, al, wo_h, wo_l, x, 0, 0, 4096, 1024, 1024, 1024, 1024, 1);
            rmsnorm_k<<<4096, 256>>>(x, ffn_norm_w + li * 1024, hh, hl, 1, 1, 0, 1024, 0);
            tgemm(hh, hl, wu_h, wu_l, 0, gh, gl, 4096, 4096, 1024, 1024, 1024, 3);
            tgemm(gh, gl, wd_h, wd_l, x, 0, 0, 4096, 1024, 2048, 2048, 2048, 1);
        }
        extract_y_k<<<(BP_ * 512 * 256 + 255) / 256, 256>>>(x, y, yh, yl);
        if (it == 0) {
            yfrms_k<<<1024, 256>>>(y, begin, pad_emb, new_norm_w, ach, acl);
            // xnew(+xnew2) = [xarn|xden|y2] @ [w_ar1|w_de1|w_y1]^T, split-K=2 (2x1536)
            tgemm_z(ach, acl, whi + (size_t)OFF_WP3 * MB1, wlo + (size_t)OFF_WP3 * MB1,
                    xnew, xnew2, 0, 0, 1024, 1024, 1536, 3072, 3072, 0, 2);
            assemble_k<<<(BP_ * S_ * 256 + 255) / 256, 256>>>(x, xold, xnew, xnew2);
        }
    }

    tgemm(yh, yl, whi + (size_t)OFF_WAGG * MB1, wlo + (size_t)OFF_WAGG * MB1,
          out, 0, 0, 1024, 1024, 1024, 1024, 1024, 0);
}